// round 6
// baseline (speedup 1.0000x reference)
#include <cuda_runtime.h>
#include <math.h>

// RotorQuantMSE — R6: R5 design with the norm-reduction bug fixed
// (4 warps per row -> 8 partials per block, combine 4 per row).
// Setup kernel bakes 256 rotor-sandwich 3x3 matrices into a __device__ table.
// Hot kernel: non-persistent, 2 rows/block (256 thr), thread owns 2 whole
// groups (6 consecutive floats) -> no selects, no data shuffles, 1 barrier.

#define D 768
#define GMAX 256

__device__ __align__(16) float g_mat[GMAX * 12];   // [G][12]: M row-major, 3 pads

__device__ __forceinline__ void rotor_apply(
    float r0, float b1, float b2, float b3,
    float v1, float v2, float v3,
    float& o1, float& o2, float& o3)
{
    float t1 = fmaf(r0, v1, fmaf(b1, v2,  b2 * v3));
    float t2 = fmaf(r0, v2, fmaf(-b1, v1, b3 * v3));
    float t3 = fmaf(r0, v3, fmaf(-b2, v1, -b3 * v2));
    float t7 = fmaf(b1, v3, fmaf(-b2, v2,  b3 * v1));
    o1 = fmaf(r0, t1, fmaf( b1, t2, fmaf( b2, t3,  b3 * t7)));
    o2 = fmaf(r0, t2, fmaf(-b1, t1, fmaf( b3, t3, -b2 * t7)));
    o3 = fmaf(r0, t3, fmaf(-b2, t1, fmaf(-b3, t2,  b1 * t7)));
}

__global__ void build_mats_kernel(const float* __restrict__ rotors, int G)
{
    int g = blockIdx.x * blockDim.x + threadIdx.x;
    if (g >= G) return;
    const float* rp = rotors + (size_t)g * 8;
    float r0 = rp[0];
    float b1 = rp[4], b2 = rp[5], b3 = rp[6];
    float M[12];
    // columns = sandwich of basis vectors; y_i = sum_j M[3i+j] v_j
    rotor_apply(r0, b1, b2, b3, 1.f, 0.f, 0.f, M[0], M[3], M[6]);
    rotor_apply(r0, b1, b2, b3, 0.f, 1.f, 0.f, M[1], M[4], M[7]);
    rotor_apply(r0, b1, b2, b3, 0.f, 0.f, 1.f, M[2], M[5], M[8]);
    M[9] = M[10] = M[11] = 0.f;
    float4* dst = reinterpret_cast<float4*>(g_mat + g * 12);
    dst[0] = make_float4(M[0], M[1], M[2], M[3]);
    dst[1] = make_float4(M[4], M[5], M[6], M[7]);
    dst[2] = make_float4(M[8], M[9], M[10], M[11]);
}

__device__ __forceinline__ int quant(float y)
{
    // argmin |y - c_k| over linspace(-1,1,16), ties -> lower index
    int k = (int)ceilf(fmaf(y + 1.0f, 7.5f, -0.5f));
    return max(0, min(15, k));
}

__global__ void __launch_bounds__(256)
rotor_quant_kernel(const float* __restrict__ x,
                   float* __restrict__ xhat,
                   float* __restrict__ idx_out,
                   float* __restrict__ norms_out,
                   int N)
{
    const int tid = threadIdx.x;
    const int s   = tid >> 7;              // row slot 0..1
    const int t   = tid & 127;             // thread in row; owns floats 6t..6t+5
    const int row = blockIdx.x * 2 + s;
    const int w   = tid >> 5;              // warp id 0..7 (4 per row)

    __shared__ float spart[8];

    // load 2 matrices for groups 2t, 2t+1 (table hot in L1/L2)
    const float4* mp = reinterpret_cast<const float4*>(g_mat + (size_t)(2 * t) * 12);
    float4 A0 = __ldg(mp + 0), A1 = __ldg(mp + 1), A2 = __ldg(mp + 2);
    float4 B0 = __ldg(mp + 3), B1 = __ldg(mp + 4), B2 = __ldg(mp + 5);
    const float MA[9] = { A0.x, A0.y, A0.z, A0.w, A1.x, A1.y, A1.z, A1.w, A2.x };
    const float MB[9] = { B0.x, B0.y, B0.z, B0.w, B1.x, B1.y, B1.z, B1.w, B2.x };

    // strided direct load: 6 floats = 3 float2 (24B offset, 8B aligned)
    const float* xr = x + (size_t)row * D + 6 * t;
    float2 u0 = __ldg(reinterpret_cast<const float2*>(xr + 0));
    float2 u1 = __ldg(reinterpret_cast<const float2*>(xr + 2));
    float2 u2 = __ldg(reinterpret_cast<const float2*>(xr + 4));
    const float v0 = u0.x, v1 = u0.y, v2 = u1.x, v3 = u1.y, v4 = u2.x, v5 = u2.y;

    // row L2 norm: warp reduce, combine the row's 4 warps via smem
    float sq = fmaf(v0, v0, fmaf(v1, v1, fmaf(v2, v2,
               fmaf(v3, v3, fmaf(v4, v4, v5 * v5)))));
    #pragma unroll
    for (int o = 16; o; o >>= 1) sq += __shfl_xor_sync(0xffffffffu, sq, o);
    if ((tid & 31) == 0) spart[w] = sq;
    __syncthreads();
    const float tot = (spart[4 * s + 0] + spart[4 * s + 1]) +
                      (spart[4 * s + 2] + spart[4 * s + 3]);
    const float nrm = fmaxf(sqrtf(tot), 1e-8f);
    const float inv = 1.0f / nrm;
    const float step = 2.0f / 15.0f;

    // group A: floats 0..2, group B: floats 3..5
    float yA0 = fmaf(MA[0], v0, fmaf(MA[1], v1, MA[2] * v2)) * inv;
    float yA1 = fmaf(MA[3], v0, fmaf(MA[4], v1, MA[5] * v2)) * inv;
    float yA2 = fmaf(MA[6], v0, fmaf(MA[7], v1, MA[8] * v2)) * inv;
    float yB0 = fmaf(MB[0], v3, fmaf(MB[1], v4, MB[2] * v5)) * inv;
    float yB1 = fmaf(MB[3], v3, fmaf(MB[4], v4, MB[5] * v5)) * inv;
    float yB2 = fmaf(MB[6], v3, fmaf(MB[7], v4, MB[8] * v5)) * inv;

    int kA0 = quant(yA0), kA1 = quant(yA1), kA2 = quant(yA2);
    int kB0 = quant(yB0), kB1 = quant(yB1), kB2 = quant(yB2);
    float qA0 = fmaf((float)kA0, step, -1.0f);
    float qA1 = fmaf((float)kA1, step, -1.0f);
    float qA2 = fmaf((float)kA2, step, -1.0f);
    float qB0 = fmaf((float)kB0, step, -1.0f);
    float qB1 = fmaf((float)kB1, step, -1.0f);
    float qB2 = fmaf((float)kB2, step, -1.0f);

    // inverse rotation = M^T, then rescale
    float h0 = fmaf(MA[0], qA0, fmaf(MA[3], qA1, MA[6] * qA2)) * nrm;
    float h1 = fmaf(MA[1], qA0, fmaf(MA[4], qA1, MA[7] * qA2)) * nrm;
    float h2 = fmaf(MA[2], qA0, fmaf(MA[5], qA1, MA[8] * qA2)) * nrm;
    float h3 = fmaf(MB[0], qB0, fmaf(MB[3], qB1, MB[6] * qB2)) * nrm;
    float h4 = fmaf(MB[1], qB0, fmaf(MB[4], qB1, MB[7] * qB2)) * nrm;
    float h5 = fmaf(MB[2], qB0, fmaf(MB[5], qB1, MB[8] * qB2)) * nrm;

    float* hr = xhat + (size_t)row * D + 6 * t;
    *reinterpret_cast<float2*>(hr + 0) = make_float2(h0, h1);
    *reinterpret_cast<float2*>(hr + 2) = make_float2(h2, h3);
    *reinterpret_cast<float2*>(hr + 4) = make_float2(h4, h5);
    if (idx_out) {
        float* ir = idx_out + (size_t)row * D + 6 * t;
        *reinterpret_cast<float2*>(ir + 0) = make_float2((float)kA0, (float)kA1);
        *reinterpret_cast<float2*>(ir + 2) = make_float2((float)kA2, (float)kB0);
        *reinterpret_cast<float2*>(ir + 4) = make_float2((float)kB1, (float)kB2);
    }
    if (t == 0 && norms_out) norms_out[row] = nrm;
}

extern "C" void kernel_launch(void* const* d_in, const int* in_sizes, int n_in,
                              void* d_out, int out_size)
{
    const float* x      = (const float*)d_in[0];   // [N, d]
    const float* rotors = (const float*)d_in[2];   // [G, 8]

    const int G = in_sizes[2] / 8;        // 256
    const int d = 3 * G;                  // 768
    const int N = in_sizes[0] / d;        // 8192

    float* out   = (float*)d_out;
    float* xhat  = out;
    float* idxp  = nullptr;
    float* normp = nullptr;
    const long nd = (long)N * d;
    if ((long)out_size >= 2 * nd)     idxp  = out + nd;
    if ((long)out_size >= 2 * nd + N) normp = out + 2 * nd;

    build_mats_kernel<<<1, 256>>>(rotors, G);
    rotor_quant_kernel<<<N / 2, 256>>>(x, xhat, idxp, normp, N);
}